// round 7
// baseline (speedup 1.0000x reference)
#include <cuda_runtime.h>
#include <cuda_bf16.h>
#include <math.h>
#include <stdint.h>

#define NTOK  32768      // n = d*h*w
#define CIN   128        // channels
#define HID   256        // heads * dim_head
#define OQKV  768        // 3 * HID
#define NB    4          // batch
#define NHEAD 8
#define DHEAD 32
#define SCALE 0.1767766952966369f  // 32^-0.5

// ---------------- scratch (device globals: allocation-free rule) ----------------
__device__ __align__(256) float g_qkv[NB * OQKV * NTOK];           // k|v fp32 (o=256..767 used)
__device__ __align__(256) float g_ksum[NB * HID];                  // per (b,h,d): sum exp(k)
__device__ __align__(256) float g_ctx[NB * NHEAD * DHEAD * DHEAD]; // raw sum exp(k)*v
__device__ __align__(256) __nv_bfloat16 g_xt_hi[NB * NTOK * CIN];  // x^T hi  [b][n][c]
__device__ __align__(256) __nv_bfloat16 g_xt_lo[NB * NTOK * CIN];  // x^T lo
__device__ __align__(256) __nv_bfloat16 g_wq_hi[OQKV * CIN];       // W_qkv hi [o][c]
__device__ __align__(256) __nv_bfloat16 g_wq_lo[OQKV * CIN];
__device__ __align__(256) __nv_bfloat16 g_qt_hi[NB * NTOK * HID];  // q_soft^T hi [b][n][hd]
__device__ __align__(256) __nv_bfloat16 g_qt_lo[NB * NTOK * HID];
__device__ __align__(256) __nv_bfloat16 g_M_hi[NB * CIN * HID];    // folded proj hi [b][co][hd]
__device__ __align__(256) __nv_bfloat16 g_M_lo[NB * CIN * HID];

// ====================== mma.sync helpers (baseline PTX, no 'a' features) ======================
__device__ __forceinline__ uint32_t smem_u32(const void* p) {
    uint32_t a;
    asm("{ .reg .u64 t; cvta.to.shared.u64 t, %1; cvt.u32.u64 %0, t; }" : "=r"(a) : "l"(p));
    return a;
}
__device__ __forceinline__ void ldsm4(uint32_t a, uint32_t* r) {
    asm volatile("ldmatrix.sync.aligned.m8n8.x4.shared.b16 {%0,%1,%2,%3}, [%4];"
                 : "=r"(r[0]), "=r"(r[1]), "=r"(r[2]), "=r"(r[3]) : "r"(a));
}
__device__ __forceinline__ void ldsm2(uint32_t a, uint32_t* r) {
    asm volatile("ldmatrix.sync.aligned.m8n8.x2.shared.b16 {%0,%1}, [%2];"
                 : "=r"(r[0]), "=r"(r[1]) : "r"(a));
}
__device__ __forceinline__ void mma_bf16(float* c, const uint32_t* a, const uint32_t* b) {
    asm volatile("mma.sync.aligned.m16n8k16.row.col.f32.bf16.bf16.f32 "
                 "{%0,%1,%2,%3}, {%4,%5,%6,%7}, {%8,%9}, {%0,%1,%2,%3};"
                 : "+f"(c[0]), "+f"(c[1]), "+f"(c[2]), "+f"(c[3])
                 : "r"(a[0]), "r"(a[1]), "r"(a[2]), "r"(a[3]), "r"(b[0]), "r"(b[1]));
}

// =====================================================================
// HMMA GEMM with bf16 hi/lo split (3 product terms, fp32 accumulate):
//   C[128 x 128] tile = A[128 x K] @ B[128 x K]^T
// 256 threads = 8 warps (2 m x 4 n), warp tile 64x32, BK=32 chunks.
// QFUSE: for m-tiles < 2 the epilogue applies the q feature-softmax
// (over each 32-row group) * SCALE and writes transposed bf16 hi/lo
// into Qhi/Qlo instead of fp32 into C.
// =====================================================================
#define LDT 40   // padded row stride in bf16 elements

template<bool BIAS, bool QFUSE>
__global__ __launch_bounds__(256, 1)
void gemm_mma_kernel(const __nv_bfloat16* __restrict__ Ahi, const __nv_bfloat16* __restrict__ Alo,
                     const __nv_bfloat16* __restrict__ Bhi, const __nv_bfloat16* __restrict__ Blo,
                     float* __restrict__ C, const float* __restrict__ bias,
                     __nv_bfloat16* __restrict__ Qhi, __nv_bfloat16* __restrict__ Qlo,
                     int K, long long sA, long long sB, long long sC)
{
    __shared__ __align__(16) __nv_bfloat16 sm[4][128 * LDT];  // Ah, Al, Bh, Bl

    const int tid = threadIdx.x, wid = tid >> 5, lane = tid & 31;
    const int nt = blockIdx.x, mt = blockIdx.y, b = blockIdx.z;

    const __nv_bfloat16* Ah = Ahi + (long long)b * sA + (long long)mt * 128 * K;
    const __nv_bfloat16* Al = Alo + (long long)b * sA + (long long)mt * 128 * K;
    const __nv_bfloat16* Bh = Bhi + (long long)b * sB + (long long)nt * 128 * K;
    const __nv_bfloat16* Bl = Blo + (long long)b * sB + (long long)nt * 128 * K;
    float* Cb = C + (long long)b * sC + (long long)mt * 128 * NTOK + (long long)nt * 128;

    const int r0c = tid >> 2,         k80 = (tid & 3) << 3;
    const int r1c = (tid + 256) >> 2, k81 = ((tid + 256) & 3) << 3;

    uint4 p[4][2];
    {
        const long long o0 = (long long)r0c * K + k80;
        const long long o1 = (long long)r1c * K + k81;
        p[0][0] = *(const uint4*)(Ah + o0); p[0][1] = *(const uint4*)(Ah + o1);
        p[1][0] = *(const uint4*)(Al + o0); p[1][1] = *(const uint4*)(Al + o1);
        p[2][0] = *(const uint4*)(Bh + o0); p[2][1] = *(const uint4*)(Bh + o1);
        p[3][0] = *(const uint4*)(Bl + o0); p[3][1] = *(const uint4*)(Bl + o1);
    }

    float acc[4][4][4];
    #pragma unroll
    for (int mi = 0; mi < 4; ++mi)
        #pragma unroll
        for (int ni = 0; ni < 4; ++ni)
            #pragma unroll
            for (int e = 0; e < 4; ++e)
                acc[mi][ni][e] = 0.f;

    const int m0 = (wid & 1) * 64;
    const int n0 = (wid >> 1) * 32;

    uint32_t baseA_h = smem_u32(&sm[0][0]);
    uint32_t baseA_l = smem_u32(&sm[1][0]);
    uint32_t baseB_h = smem_u32(&sm[2][0]);
    uint32_t baseB_l = smem_u32(&sm[3][0]);

    const int d0 = r0c * LDT + k80;
    const int d1 = r1c * LDT + k81;

    const int nkc = K >> 5;
    for (int kc = 0; kc < nkc; ++kc) {
        #pragma unroll
        for (int t = 0; t < 4; ++t) {
            *(uint4*)&sm[t][d0] = p[t][0];
            *(uint4*)&sm[t][d1] = p[t][1];
        }
        __syncthreads();

        if (kc + 1 < nkc) {
            const long long o0 = (long long)r0c * K + (kc + 1) * 32 + k80;
            const long long o1 = (long long)r1c * K + (kc + 1) * 32 + k81;
            p[0][0] = *(const uint4*)(Ah + o0); p[0][1] = *(const uint4*)(Ah + o1);
            p[1][0] = *(const uint4*)(Al + o0); p[1][1] = *(const uint4*)(Al + o1);
            p[2][0] = *(const uint4*)(Bh + o0); p[2][1] = *(const uint4*)(Bh + o1);
            p[3][0] = *(const uint4*)(Bl + o0); p[3][1] = *(const uint4*)(Bl + o1);
        }

        #pragma unroll
        for (int s = 0; s < 2; ++s) {
            const uint32_t aoff = (uint32_t)((m0 + (lane & 15)) * (LDT * 2)
                                 + s * 32 + ((lane >> 4) << 4));
            const uint32_t boff = (uint32_t)((n0 + (lane & 7)) * (LDT * 2)
                                 + s * 32 + (((lane >> 3) & 1) << 4));
            uint32_t ah[4][4], al[4][4], bh[4][2], bl[4][2];
            #pragma unroll
            for (int mi = 0; mi < 4; ++mi) {
                ldsm4(baseA_h + aoff + mi * 16 * (LDT * 2), ah[mi]);
                ldsm4(baseA_l + aoff + mi * 16 * (LDT * 2), al[mi]);
            }
            #pragma unroll
            for (int ni = 0; ni < 4; ++ni) {
                ldsm2(baseB_h + boff + ni * 8 * (LDT * 2), bh[ni]);
                ldsm2(baseB_l + boff + ni * 8 * (LDT * 2), bl[ni]);
            }
            #pragma unroll
            for (int mi = 0; mi < 4; ++mi)
                #pragma unroll
                for (int ni = 0; ni < 4; ++ni) {
                    mma_bf16(acc[mi][ni], ah[mi], bh[ni]);
                    mma_bf16(acc[mi][ni], al[mi], bh[ni]);
                    mma_bf16(acc[mi][ni], ah[mi], bl[ni]);
                }
        }
        __syncthreads();
    }

    if (QFUSE && mt < 2) {
        // ---- fused q softmax over each 32-row feature group, * SCALE ----
        #pragma unroll
        for (int g = 0; g < 2; ++g) {
            #pragma unroll
            for (int ni = 0; ni < 4; ++ni) {
                #pragma unroll
                for (int par = 0; par < 2; ++par) {
                    float v0 = acc[2 * g][ni][par],     v1 = acc[2 * g][ni][par + 2];
                    float v2 = acc[2 * g + 1][ni][par], v3 = acc[2 * g + 1][ni][par + 2];
                    float m = fmaxf(fmaxf(v0, v1), fmaxf(v2, v3));
                    #pragma unroll
                    for (int o = 4; o <= 16; o <<= 1)
                        m = fmaxf(m, __shfl_xor_sync(0xffffffffu, m, o));
                    v0 = __expf(v0 - m); v1 = __expf(v1 - m);
                    v2 = __expf(v2 - m); v3 = __expf(v3 - m);
                    float s = (v0 + v1) + (v2 + v3);
                    #pragma unroll
                    for (int o = 4; o <= 16; o <<= 1)
                        s += __shfl_xor_sync(0xffffffffu, s, o);
                    const float inv = SCALE / s;
                    acc[2 * g][ni][par]         = v0 * inv;
                    acc[2 * g][ni][par + 2]     = v1 * inv;
                    acc[2 * g + 1][ni][par]     = v2 * inv;
                    acc[2 * g + 1][ni][par + 2] = v3 * inv;
                }
            }
        }
        // ---- transpose-stage through (dead) smem tiles, write bf16 hi/lo ----
        __nv_bfloat16* S = &sm[0][0];   // 128 n x 128 hd-local
        #pragma unroll
        for (int pass = 0; pass < 2; ++pass) {
            #pragma unroll
            for (int mi = 0; mi < 4; ++mi)
                #pragma unroll
                for (int ni = 0; ni < 4; ++ni)
                    #pragma unroll
                    for (int c = 0; c < 4; ++c) {
                        const int row = m0 + mi * 16 + (lane >> 2) + ((c >> 1) << 3);
                        const int col = n0 + ni * 8 + ((lane & 3) << 1) + (c & 1);
                        const float q = acc[mi][ni][c];
                        const __nv_bfloat16 h = __float2bfloat16(q);
                        S[col * 128 + row] = (pass == 0)
                            ? h : __float2bfloat16(q - __bfloat162float(h));
                    }
            __syncthreads();
            __nv_bfloat16* dst = (pass == 0 ? Qhi : Qlo)
                + ((long long)b * NTOK + (long long)nt * 128) * HID + mt * 128;
            #pragma unroll
            for (int i = 0; i < 8; ++i) {
                const int cid = tid + i * 256;
                const int n = cid >> 4, off = (cid & 15) << 3;
                *(uint4*)(dst + (long long)n * HID + off) = *(const uint4*)(S + n * 128 + off);
            }
            __syncthreads();
        }
        return;
    }

    // ---- fp32 epilogue (k/v tiles and GEMM2) ----
    #pragma unroll
    for (int mi = 0; mi < 4; ++mi) {
        const int r = m0 + mi * 16 + (lane >> 2);
        const float bv0 = BIAS ? bias[mt * 128 + r] : 0.f;
        const float bv1 = BIAS ? bias[mt * 128 + r + 8] : 0.f;
        #pragma unroll
        for (int ni = 0; ni < 4; ++ni) {
            const int cc = n0 + ni * 8 + ((lane & 3) << 1);
            float2 v0 = make_float2(acc[mi][ni][0] + bv0, acc[mi][ni][1] + bv0);
            float2 v1 = make_float2(acc[mi][ni][2] + bv1, acc[mi][ni][3] + bv1);
            *(float2*)(Cb + (long long)r * NTOK + cc)       = v0;
            *(float2*)(Cb + (long long)(r + 8) * NTOK + cc) = v1;
        }
    }
}

// =====================================================================
// x [b][c][n] fp32 -> x^T hi/lo bf16 [b][n][c]   (32x32 smem transpose)
// =====================================================================
__global__ void convx_kernel(const float* __restrict__ x)
{
    __shared__ float t[32][33];
    const int n0 = blockIdx.x * 32, c0 = blockIdx.y * 32, b = blockIdx.z;
    const int tx = threadIdx.x, ty = threadIdx.y;
    const float* xb = x + ((long long)b * CIN + c0) * NTOK + n0;
    #pragma unroll
    for (int i = 0; i < 4; ++i)
        t[ty + i * 8][tx] = xb[(long long)(ty + i * 8) * NTOK + tx];
    __syncthreads();
    #pragma unroll
    for (int i = 0; i < 4; ++i) {
        const int n = ty + i * 8;
        const float v = t[tx][n];
        const __nv_bfloat16 hi = __float2bfloat16(v);
        const __nv_bfloat16 lo = __float2bfloat16(v - __bfloat162float(hi));
        const long long o = ((long long)b * NTOK + n0 + n) * CIN + c0 + tx;
        g_xt_hi[o] = hi;
        g_xt_lo[o] = lo;
    }
}

// W_qkv [768][128] fp32 -> hi/lo bf16 same layout
__global__ void convw_kernel(const float* __restrict__ w)
{
    const int i = blockIdx.x * 256 + threadIdx.x;
    const float v = w[i];
    const __nv_bfloat16 hi = __float2bfloat16(v);
    g_wq_hi[i] = hi;
    g_wq_lo[i] = __float2bfloat16(v - __bfloat162float(hi));
}

// =====================================================================
// context: ctx[b,h,d,e] += sum_n exp(k[d,n]) * v[e,n];  ksum += sum exp(k)
// (no max subtraction: k ~ N(0,1); the exp(-max) cancels in mcombine)
// =====================================================================
__global__ __launch_bounds__(256, 2)
void context_kernel()
{
    const int b = blockIdx.z, h = blockIdx.y, cx = blockIdx.x;
    const int t = threadIdx.x;
    const float* kbase = g_qkv + ((long long)b * OQKV + HID     + h * DHEAD) * NTOK;
    const float* vbase = g_qkv + ((long long)b * OQKV + 2 * HID + h * DHEAD) * NTOK;

    __shared__ float ks[32][33];
    __shared__ float vs[32][33];
    __shared__ float red[32][33];

    for (int i = t; i < 1024; i += 256) red[i >> 5][i & 31] = 0.f;

    const int ld = t >> 3;
    const int ln = (t & 7) << 2;
    const int slot = t >> 4;
    const int l    = t & 15;
    const int ti   = l >> 2;
    const int tj   = l & 3;

    float acc[8][8];
    #pragma unroll
    for (int i = 0; i < 8; ++i)
        #pragma unroll
        for (int j = 0; j < 8; ++j)
            acc[i][j] = 0.f;
    float ksum_part = 0.f;

    const int nbase0 = cx * (NTOK / 32);     // 1024-wide chunk, 32 chunks
    const int NS = (NTOK / 32) / 32;         // 32 slabs of 32 n

    const float* krow = kbase + (long long)ld * NTOK + nbase0 + ln;
    const float* vrow = vbase + (long long)ld * NTOK + nbase0 + ln;
    float4 kr = *(const float4*)krow;
    float4 vr = *(const float4*)vrow;

    for (int slab = 0; slab < NS; ++slab) {
        const float e0 = __expf(kr.x), e1 = __expf(kr.y);
        const float e2 = __expf(kr.z), e3 = __expf(kr.w);
        ksum_part += (e0 + e1) + (e2 + e3);
        ks[ld][ln] = e0; ks[ld][ln + 1] = e1; ks[ld][ln + 2] = e2; ks[ld][ln + 3] = e3;
        vs[ld][ln] = vr.x; vs[ld][ln + 1] = vr.y; vs[ld][ln + 2] = vr.z; vs[ld][ln + 3] = vr.w;
        __syncthreads();

        if (slab + 1 < NS) {
            kr = *(const float4*)(krow + (slab + 1) * 32);
            vr = *(const float4*)(vrow + (slab + 1) * 32);
        }

        #pragma unroll
        for (int q = 0; q < 2; ++q) {
            const int n = slot * 2 + q;
            float ka[8], va[8];
            #pragma unroll
            for (int i = 0; i < 8; ++i) ka[i] = ks[ti * 8 + i][n];
            #pragma unroll
            for (int j = 0; j < 8; ++j) va[j] = vs[tj * 8 + j][n];
            #pragma unroll
            for (int i = 0; i < 8; ++i)
                #pragma unroll
                for (int j = 0; j < 8; ++j)
                    acc[i][j] = fmaf(ka[i], va[j], acc[i][j]);
        }
        __syncthreads();
    }

    #pragma unroll
    for (int o = 4; o > 0; o >>= 1)
        ksum_part += __shfl_down_sync(0xffffffffu, ksum_part, o, 8);
    if ((t & 7) == 0)
        atomicAdd(&g_ksum[(b * NHEAD + h) * DHEAD + ld], ksum_part);

    #pragma unroll
    for (int i = 0; i < 8; ++i)
        #pragma unroll
        for (int j = 0; j < 8; ++j)
            atomicAdd(&red[ti * 8 + i][tj * 8 + j], acc[i][j]);
    __syncthreads();

    float* ctx = g_ctx + (b * NHEAD + h) * (DHEAD * DHEAD);
    for (int i = t; i < 1024; i += 256)
        atomicAdd(&ctx[i], red[i >> 5][i & 31]);
}

// =====================================================================
// M[b][co][h*32+d] = (sum_e W_out[co][h*32+e] * ctx[b,h,d,e]) / ksum[b,h,d]
// emitted as bf16 hi/lo for GEMM2's A operand.
// =====================================================================
__global__ void mcombine_kernel(const float* __restrict__ w_out)
{
    const int idx = blockIdx.x * 256 + threadIdx.x;   // 4*128*256
    const int col = idx & 255;
    const int co  = (idx >> 8) & 127;
    const int b   = idx >> 15;
    const int h = col >> 5, d = col & 31;

    const float* wrow = w_out + co * HID + h * DHEAD;
    const float* cr = g_ctx + ((b * NHEAD + h) * DHEAD + d) * DHEAD;
    float s = 0.f;
    #pragma unroll
    for (int e = 0; e < 32; ++e) s = fmaf(wrow[e], cr[e], s);
    const float m = s / g_ksum[b * HID + col];

    const long long o = ((long long)b * CIN + co) * HID + col;
    const __nv_bfloat16 hi = __float2bfloat16(m);
    g_M_hi[o] = hi;
    g_M_lo[o] = __float2bfloat16(m - __bfloat162float(hi));
}

// =====================================================================
extern "C" void kernel_launch(void* const* d_in, const int* in_sizes, int n_in,
                              void* d_out, int out_size)
{
    const float* x     = (const float*)d_in[0];   // [4,128,32768]
    const float* w_qkv = (const float*)d_in[1];   // [768,128]
    const float* w_out = (const float*)d_in[2];   // [128,256]
    const float* b_out = (const float*)d_in[3];   // [128]
    float* out = (float*)d_out;                   // [4,128,32768]

    float *qkv_p = nullptr, *ctx_p = nullptr, *ksum_p = nullptr;
    __nv_bfloat16 *xth, *xtl, *wqh, *wql, *qth, *qtl, *mh, *ml;
    cudaGetSymbolAddress((void**)&qkv_p, g_qkv);
    cudaGetSymbolAddress((void**)&ctx_p, g_ctx);
    cudaGetSymbolAddress((void**)&ksum_p, g_ksum);
    cudaGetSymbolAddress((void**)&xth, g_xt_hi);
    cudaGetSymbolAddress((void**)&xtl, g_xt_lo);
    cudaGetSymbolAddress((void**)&wqh, g_wq_hi);
    cudaGetSymbolAddress((void**)&wql, g_wq_lo);
    cudaGetSymbolAddress((void**)&qth, g_qt_hi);
    cudaGetSymbolAddress((void**)&qtl, g_qt_lo);
    cudaGetSymbolAddress((void**)&mh, g_M_hi);
    cudaGetSymbolAddress((void**)&ml, g_M_lo);

    // 0) convert inputs to bf16 hi/lo (x transposed)
    convx_kernel<<<dim3(NTOK / 32, CIN / 32, NB), dim3(32, 8)>>>(x);
    convw_kernel<<<(OQKV * CIN) / 256, 256>>>(w_qkv);

    // 1) qkv GEMM (HMMA, 3-term bf16 split):
    //    m-tiles 0-1 -> fused q softmax, bf16 hi/lo qt out
    //    m-tiles 2-5 -> k,v fp32 into g_qkv
    gemm_mma_kernel<false, true><<<dim3(NTOK / 128, OQKV / 128, NB), 256>>>(
        wqh, wql, xth, xtl, qkv_p, nullptr, qth, qtl, CIN,
        0LL, (long long)NTOK * CIN, (long long)OQKV * NTOK);

    // 2) zero accumulators
    cudaMemsetAsync(ctx_p, 0, sizeof(float) * NB * NHEAD * DHEAD * DHEAD);
    cudaMemsetAsync(ksum_p, 0, sizeof(float) * NB * HID);

    // 3) context + ksum
    context_kernel<<<dim3(32, NHEAD, NB), 256>>>();

    // 4) fold projection matrix -> bf16 hi/lo
    mcombine_kernel<<<(NB * CIN * HID) / 256, 256>>>(w_out);

    // 5) out = M @ q_soft + b_out  (HMMA, K=256)
    gemm_mma_kernel<true, false><<<dim3(NTOK / 128, 1, NB), 256>>>(
        mh, ml, qth, qtl, out, b_out, nullptr, nullptr, HID,
        (long long)CIN * HID, (long long)NTOK * HID, (long long)CIN * NTOK);
}

// round 9
// speedup vs baseline: 1.0655x; 1.0655x over previous
#include <cuda_runtime.h>
#include <cuda_bf16.h>
#include <math.h>
#include <stdint.h>

#define NTOK  32768      // n = d*h*w
#define CIN   128        // channels
#define HID   256        // heads * dim_head
#define OQKV  768        // 3 * HID
#define NB    4          // batch
#define NHEAD 8
#define DHEAD 32
#define SCALE 0.1767766952966369f  // 32^-0.5

// ---------------- scratch (device globals: allocation-free rule) ----------------
__device__ __align__(256) float g_qkv[NB * OQKV * NTOK];           // q|k|v fp32, [b][o][n]
__device__ __align__(256) float g_ksum[NB * HID];                  // per (b,h,d): sum exp(k)
__device__ __align__(256) float g_ctx[NB * NHEAD * DHEAD * DHEAD]; // raw sum exp(k)*v
__device__ __align__(256) __nv_bfloat16 g_xt_hi[NB * NTOK * CIN];  // x^T hi  [b][n][c]
__device__ __align__(256) __nv_bfloat16 g_xt_lo[NB * NTOK * CIN];  // x^T lo
__device__ __align__(256) __nv_bfloat16 g_wq_hi[OQKV * CIN];       // W_qkv hi [o][c]
__device__ __align__(256) __nv_bfloat16 g_wq_lo[OQKV * CIN];
__device__ __align__(256) __nv_bfloat16 g_qt_hi[NB * NTOK * HID];  // q_soft^T hi [b][n][hd]
__device__ __align__(256) __nv_bfloat16 g_qt_lo[NB * NTOK * HID];
__device__ __align__(256) __nv_bfloat16 g_M_hi[NB * CIN * HID];    // folded proj hi [b][co][hd]
__device__ __align__(256) __nv_bfloat16 g_M_lo[NB * CIN * HID];

// ====================== mma.sync helpers (baseline PTX, no 'a' features) ======================
__device__ __forceinline__ uint32_t smem_u32(const void* p) {
    uint32_t a;
    asm("{ .reg .u64 t; cvta.to.shared.u64 t, %1; cvt.u32.u64 %0, t; }" : "=r"(a) : "l"(p));
    return a;
}
__device__ __forceinline__ void ldsm4(uint32_t a, uint32_t* r) {
    asm volatile("ldmatrix.sync.aligned.m8n8.x4.shared.b16 {%0,%1,%2,%3}, [%4];"
                 : "=r"(r[0]), "=r"(r[1]), "=r"(r[2]), "=r"(r[3]) : "r"(a));
}
__device__ __forceinline__ void ldsm2(uint32_t a, uint32_t* r) {
    asm volatile("ldmatrix.sync.aligned.m8n8.x2.shared.b16 {%0,%1}, [%2];"
                 : "=r"(r[0]), "=r"(r[1]) : "r"(a));
}
__device__ __forceinline__ void mma_bf16(float* c, const uint32_t* a, const uint32_t* b) {
    asm volatile("mma.sync.aligned.m16n8k16.row.col.f32.bf16.bf16.f32 "
                 "{%0,%1,%2,%3}, {%4,%5,%6,%7}, {%8,%9}, {%0,%1,%2,%3};"
                 : "+f"(c[0]), "+f"(c[1]), "+f"(c[2]), "+f"(c[3])
                 : "r"(a[0]), "r"(a[1]), "r"(a[2]), "r"(a[3]), "r"(b[0]), "r"(b[1]));
}

// =====================================================================
// HMMA GEMM with bf16 hi/lo split (3 product terms, fp32 accumulate):
//   C[128 x 128] tile = A[128 x K] @ B[128 x K]^T
// A row-major [m][k], B row-major [n][k] (both hi/lo bf16).
// 256 threads = 8 warps (2 m x 4 n), warp tile 64x32, BK=32 chunks with
// register-prefetch. Smem rows padded to 40 elems (80B) -> conflict-free
// ldmatrix. C fp32, leading dim NTOK. Grid (n-tiles, m-tiles, NB).
// =====================================================================
#define LDT 40   // padded row stride in bf16 elements

template<bool BIAS>
__global__ __launch_bounds__(256, 1)
void gemm_mma_kernel(const __nv_bfloat16* __restrict__ Ahi, const __nv_bfloat16* __restrict__ Alo,
                     const __nv_bfloat16* __restrict__ Bhi, const __nv_bfloat16* __restrict__ Blo,
                     float* __restrict__ C, const float* __restrict__ bias, int K,
                     long long sA, long long sB, long long sC)
{
    __shared__ __align__(16) __nv_bfloat16 sm[4][128 * LDT];  // Ah, Al, Bh, Bl

    const int tid = threadIdx.x, wid = tid >> 5, lane = tid & 31;
    const int nt = blockIdx.x, mt = blockIdx.y, b = blockIdx.z;

    const __nv_bfloat16* Ah = Ahi + (long long)b * sA + (long long)mt * 128 * K;
    const __nv_bfloat16* Al = Alo + (long long)b * sA + (long long)mt * 128 * K;
    const __nv_bfloat16* Bh = Bhi + (long long)b * sB + (long long)nt * 128 * K;
    const __nv_bfloat16* Bl = Blo + (long long)b * sB + (long long)nt * 128 * K;
    float* Cb = C + (long long)b * sC + (long long)mt * 128 * NTOK + (long long)nt * 128;

    const int r0c = tid >> 2,         k80 = (tid & 3) << 3;
    const int r1c = (tid + 256) >> 2, k81 = ((tid + 256) & 3) << 3;

    uint4 p[4][2];
    {
        const long long o0 = (long long)r0c * K + k80;
        const long long o1 = (long long)r1c * K + k81;
        p[0][0] = *(const uint4*)(Ah + o0); p[0][1] = *(const uint4*)(Ah + o1);
        p[1][0] = *(const uint4*)(Al + o0); p[1][1] = *(const uint4*)(Al + o1);
        p[2][0] = *(const uint4*)(Bh + o0); p[2][1] = *(const uint4*)(Bh + o1);
        p[3][0] = *(const uint4*)(Bl + o0); p[3][1] = *(const uint4*)(Bl + o1);
    }

    float acc[4][4][4];
    #pragma unroll
    for (int mi = 0; mi < 4; ++mi)
        #pragma unroll
        for (int ni = 0; ni < 4; ++ni)
            #pragma unroll
            for (int e = 0; e < 4; ++e)
                acc[mi][ni][e] = 0.f;

    const int m0 = (wid & 1) * 64;
    const int n0 = (wid >> 1) * 32;

    uint32_t baseA_h = smem_u32(&sm[0][0]);
    uint32_t baseA_l = smem_u32(&sm[1][0]);
    uint32_t baseB_h = smem_u32(&sm[2][0]);
    uint32_t baseB_l = smem_u32(&sm[3][0]);

    const int d0 = r0c * LDT + k80;
    const int d1 = r1c * LDT + k81;

    const int nkc = K >> 5;
    for (int kc = 0; kc < nkc; ++kc) {
        #pragma unroll
        for (int t = 0; t < 4; ++t) {
            *(uint4*)&sm[t][d0] = p[t][0];
            *(uint4*)&sm[t][d1] = p[t][1];
        }
        __syncthreads();

        if (kc + 1 < nkc) {
            const long long o0 = (long long)r0c * K + (kc + 1) * 32 + k80;
            const long long o1 = (long long)r1c * K + (kc + 1) * 32 + k81;
            p[0][0] = *(const uint4*)(Ah + o0); p[0][1] = *(const uint4*)(Ah + o1);
            p[1][0] = *(const uint4*)(Al + o0); p[1][1] = *(const uint4*)(Al + o1);
            p[2][0] = *(const uint4*)(Bh + o0); p[2][1] = *(const uint4*)(Bh + o1);
            p[3][0] = *(const uint4*)(Bl + o0); p[3][1] = *(const uint4*)(Bl + o1);
        }

        #pragma unroll
        for (int s = 0; s < 2; ++s) {
            const uint32_t aoff = (uint32_t)((m0 + (lane & 15)) * (LDT * 2)
                                 + s * 32 + ((lane >> 4) << 4));
            const uint32_t boff = (uint32_t)((n0 + (lane & 7)) * (LDT * 2)
                                 + s * 32 + (((lane >> 3) & 1) << 4));
            uint32_t ah[4][4], al[4][4], bh[4][2], bl[4][2];
            #pragma unroll
            for (int mi = 0; mi < 4; ++mi) {
                ldsm4(baseA_h + aoff + mi * 16 * (LDT * 2), ah[mi]);
                ldsm4(baseA_l + aoff + mi * 16 * (LDT * 2), al[mi]);
            }
            #pragma unroll
            for (int ni = 0; ni < 4; ++ni) {
                ldsm2(baseB_h + boff + ni * 8 * (LDT * 2), bh[ni]);
                ldsm2(baseB_l + boff + ni * 8 * (LDT * 2), bl[ni]);
            }
            #pragma unroll
            for (int mi = 0; mi < 4; ++mi)
                #pragma unroll
                for (int ni = 0; ni < 4; ++ni) {
                    mma_bf16(acc[mi][ni], ah[mi], bh[ni]);
                    mma_bf16(acc[mi][ni], al[mi], bh[ni]);
                    mma_bf16(acc[mi][ni], ah[mi], bl[ni]);
                }
        }
        __syncthreads();
    }

    // epilogue: thread holds rows (m0+mi*16 + lane/4, +8), cols (n0+ni*8 + (lane%4)*2, +1)
    #pragma unroll
    for (int mi = 0; mi < 4; ++mi) {
        const int r = m0 + mi * 16 + (lane >> 2);
        const float bv0 = BIAS ? bias[mt * 128 + r] : 0.f;
        const float bv1 = BIAS ? bias[mt * 128 + r + 8] : 0.f;
        #pragma unroll
        for (int ni = 0; ni < 4; ++ni) {
            const int cc = n0 + ni * 8 + ((lane & 3) << 1);
            float2 v0 = make_float2(acc[mi][ni][0] + bv0, acc[mi][ni][1] + bv0);
            float2 v1 = make_float2(acc[mi][ni][2] + bv1, acc[mi][ni][3] + bv1);
            *(float2*)(Cb + (long long)r * NTOK + cc)       = v0;
            *(float2*)(Cb + (long long)(r + 8) * NTOK + cc) = v1;
        }
    }
}

// =====================================================================
// x [b][c][n] fp32 -> x^T hi/lo bf16 [b][n][c]   (32x32 smem transpose)
// =====================================================================
__global__ void convx_kernel(const float* __restrict__ x)
{
    __shared__ float t[32][33];
    const int n0 = blockIdx.x * 32, c0 = blockIdx.y * 32, b = blockIdx.z;
    const int tx = threadIdx.x, ty = threadIdx.y;
    const float* xb = x + ((long long)b * CIN + c0) * NTOK + n0;
    #pragma unroll
    for (int i = 0; i < 4; ++i)
        t[ty + i * 8][tx] = xb[(long long)(ty + i * 8) * NTOK + tx];
    __syncthreads();
    #pragma unroll
    for (int i = 0; i < 4; ++i) {
        const int n = ty + i * 8;
        const float v = t[tx][n];
        const __nv_bfloat16 hi = __float2bfloat16(v);
        const __nv_bfloat16 lo = __float2bfloat16(v - __bfloat162float(hi));
        const long long o = ((long long)b * NTOK + n0 + n) * CIN + c0 + tx;
        g_xt_hi[o] = hi;
        g_xt_lo[o] = lo;
    }
}

// W_qkv [768][128] fp32 -> hi/lo bf16 same layout
__global__ void convw_kernel(const float* __restrict__ w)
{
    const int i = blockIdx.x * 256 + threadIdx.x;
    const float v = w[i];
    const __nv_bfloat16 hi = __float2bfloat16(v);
    g_wq_hi[i] = hi;
    g_wq_lo[i] = __float2bfloat16(v - __bfloat162float(hi));
}

// =====================================================================
// q softmax over 32 feature dims per head, * SCALE; writes transposed
// bf16 hi/lo [b][n][h*32+d] with smem staging for coalesced stores.
// Block 256 = 8 heads (warp each) x 32 tokens. Grid (NTOK/32, NB).
// =====================================================================
__global__ __launch_bounds__(256, 4)
void qsoftmax_kernel()
{
    __shared__ uint32_t sh[32][133];   // [token][packed bf16 pair], pad 133 (5 mod 32 coprime)

    const int b  = blockIdx.y;
    const int n0 = blockIdx.x * 32;
    const int t  = threadIdx.x;
    const int h  = t >> 5, nl = t & 31;

    const float* qp = g_qkv + ((long long)b * OQKV + (long long)h * DHEAD) * NTOK + n0 + nl;

    float v[32];
    float m = -1e30f;
    #pragma unroll
    for (int d = 0; d < 32; ++d) {
        v[d] = qp[(long long)d * NTOK];
        m = fmaxf(m, v[d]);
    }
    float s = 0.f;
    #pragma unroll
    for (int d = 0; d < 32; ++d) {
        v[d] = __expf(v[d] - m);
        s += v[d];
    }
    const float inv = SCALE / s;
    #pragma unroll
    for (int d = 0; d < 32; ++d)
        v[d] *= inv;                  // final q value (fp32)

    // output thread mapping: row r (token), 16 packed words starting at c0
    const int r  = t >> 3;
    const int c0 = (t & 7) << 4;
    uint32_t* dst_hi = (uint32_t*)g_qt_hi + ((long long)b * NTOK + n0 + r) * (HID / 2) + c0;
    uint32_t* dst_lo = (uint32_t*)g_qt_lo + ((long long)b * NTOK + n0 + r) * (HID / 2) + c0;

    #pragma unroll
    for (int pass = 0; pass < 2; ++pass) {
        // pack hi (pass 0) or lo (pass 1) pairs into smem
        #pragma unroll
        for (int d2 = 0; d2 < 16; ++d2) {
            const float q0 = v[2 * d2], q1 = v[2 * d2 + 1];
            __nv_bfloat16 x0 = __float2bfloat16(q0);
            __nv_bfloat16 x1 = __float2bfloat16(q1);
            if (pass) {
                x0 = __float2bfloat16(q0 - __bfloat162float(x0));
                x1 = __float2bfloat16(q1 - __bfloat162float(x1));
            }
            const uint32_t w = (uint32_t)*(uint16_t*)&x0 | ((uint32_t)*(uint16_t*)&x1 << 16);
            sh[nl][h * 16 + d2] = w;
        }
        __syncthreads();

        // coalesced store: each thread 4x uint4 = 64B; 8 threads cover a 512B row
        #pragma unroll
        for (int c = 0; c < 4; ++c) {
            uint4 o;
            o.x = sh[r][c0 + c * 4 + 0];
            o.y = sh[r][c0 + c * 4 + 1];
            o.z = sh[r][c0 + c * 4 + 2];
            o.w = sh[r][c0 + c * 4 + 3];
            *(uint4*)((pass == 0 ? dst_hi : dst_lo) + c * 4) = o;
        }
        __syncthreads();
    }
}

// =====================================================================
// context: ctx[b,h,d,e] += sum_n exp(k[d,n]) * v[e,n];  ksum += sum exp(k)
// (no max subtraction: k ~ N(0,1); the exp(-max) cancels in mcombine)
// FFMA2 inner loop: acc pairs packed along e via transposed v tile.
// 64-token slabs (half the barriers of the 32-slab version).
// Grid (32 n-chunks, NHEAD, NB), 256 threads.
// =====================================================================
__global__ __launch_bounds__(256, 2)
void context_kernel()
{
    const int b = blockIdx.z, h = blockIdx.y, cx = blockIdx.x;
    const int t = threadIdx.x;
    const float* kbase = g_qkv + ((long long)b * OQKV + HID     + h * DHEAD) * NTOK;
    const float* vbase = g_qkv + ((long long)b * OQKV + 2 * HID + h * DHEAD) * NTOK;

    __shared__ float ks[32][65];   // [d][n]  (odd pad: conflict-free column reads)
    __shared__ float vt[64][34];   // [n][e]  (even pad: aligned LDS.64 pairs)
    __shared__ float red[32][33];

    for (int i = t; i < 1024; i += 256) red[i >> 5][i & 31] = 0.f;

    // loader: row ld (0..31), 8 consecutive n at ln
    const int ld = t >> 3;
    const int ln = (t & 7) << 3;

    // compute: slot handles n = slot + 16*q (q=0..3); 16 threads = 4x4 of 8x8
    const int slot = t >> 4;
    const int l    = t & 15;
    const int ti   = l >> 2;          // d-tile
    const int tj   = l & 3;           // e-tile

    unsigned long long accp[8][4];    // [d-row][e-pair]
    #pragma unroll
    for (int i = 0; i < 8; ++i)
        #pragma unroll
        for (int j = 0; j < 4; ++j)
            accp[i][j] = 0ULL;
    float ksum_part = 0.f;

    const int nchunk = NTOK / 32;     // 1024 n per CTA
    const int nbase0 = cx * nchunk;
    const int NS = nchunk / 64;       // 16 slabs of 64 n

    const float* krow = kbase + (long long)ld * NTOK + nbase0 + ln;
    const float* vrow = vbase + (long long)ld * NTOK + nbase0 + ln;
    float4 kr0 = *(const float4*)krow, kr1 = *(const float4*)(krow + 4);
    float4 vr0 = *(const float4*)vrow, vr1 = *(const float4*)(vrow + 4);

    for (int slab = 0; slab < NS; ++slab) {
        const float e0 = __expf(kr0.x), e1 = __expf(kr0.y);
        const float e2 = __expf(kr0.z), e3 = __expf(kr0.w);
        const float e4 = __expf(kr1.x), e5 = __expf(kr1.y);
        const float e6 = __expf(kr1.z), e7 = __expf(kr1.w);
        ksum_part += ((e0 + e1) + (e2 + e3)) + ((e4 + e5) + (e6 + e7));
        ks[ld][ln + 0] = e0; ks[ld][ln + 1] = e1; ks[ld][ln + 2] = e2; ks[ld][ln + 3] = e3;
        ks[ld][ln + 4] = e4; ks[ld][ln + 5] = e5; ks[ld][ln + 6] = e6; ks[ld][ln + 7] = e7;
        vt[ln + 0][ld] = vr0.x; vt[ln + 1][ld] = vr0.y;
        vt[ln + 2][ld] = vr0.z; vt[ln + 3][ld] = vr0.w;
        vt[ln + 4][ld] = vr1.x; vt[ln + 5][ld] = vr1.y;
        vt[ln + 6][ld] = vr1.z; vt[ln + 7][ld] = vr1.w;
        __syncthreads();

        if (slab + 1 < NS) {
            const float* kn = krow + (slab + 1) * 64;
            const float* vn = vrow + (slab + 1) * 64;
            kr0 = *(const float4*)kn; kr1 = *(const float4*)(kn + 4);
            vr0 = *(const float4*)vn; vr1 = *(const float4*)(vn + 4);
        }

        #pragma unroll
        for (int q = 0; q < 4; ++q) {
            const int n = slot + (q << 4);
            unsigned long long a2[8];
            #pragma unroll
            for (int i = 0; i < 8; ++i) {
                const float ka = ks[ti * 8 + i][n];
                asm("mov.b64 %0, {%1, %1};" : "=l"(a2[i]) : "f"(ka));
            }
            unsigned long long vb[4];
            #pragma unroll
            for (int j = 0; j < 4; ++j)
                vb[j] = *(const unsigned long long*)&vt[n][tj * 8 + 2 * j];
            #pragma unroll
            for (int i = 0; i < 8; ++i)
                #pragma unroll
                for (int j = 0; j < 4; ++j)
                    asm("fma.rn.f32x2 %0, %1, %2, %0;"
                        : "+l"(accp[i][j]) : "l"(a2[i]), "l"(vb[j]));
        }
        __syncthreads();
    }

    // ksum: reduce over the 8 loader threads sharing row ld (consecutive lanes)
    #pragma unroll
    for (int o = 4; o > 0; o >>= 1)
        ksum_part += __shfl_down_sync(0xffffffffu, ksum_part, o, 8);
    if ((t & 7) == 0)
        atomicAdd(&g_ksum[(b * NHEAD + h) * DHEAD + ld], ksum_part);

    #pragma unroll
    for (int i = 0; i < 8; ++i)
        #pragma unroll
        for (int j = 0; j < 4; ++j) {
            float f0, f1;
            asm("mov.b64 {%0, %1}, %2;" : "=f"(f0), "=f"(f1) : "l"(accp[i][j]));
            atomicAdd(&red[ti * 8 + i][tj * 8 + 2 * j],     f0);
            atomicAdd(&red[ti * 8 + i][tj * 8 + 2 * j + 1], f1);
        }
    __syncthreads();

    float* ctx = g_ctx + (b * NHEAD + h) * (DHEAD * DHEAD);
    for (int i = t; i < 1024; i += 256)
        atomicAdd(&ctx[i], red[i >> 5][i & 31]);
}

// =====================================================================
// M[b][co][h*32+d] = (sum_e W_out[co][h*32+e] * ctx[b,h,d,e]) / ksum[b,h,d]
// emitted as bf16 hi/lo for GEMM2's A operand.
// =====================================================================
__global__ void mcombine_kernel(const float* __restrict__ w_out)
{
    const int idx = blockIdx.x * 256 + threadIdx.x;   // 4*128*256
    const int col = idx & 255;
    const int co  = (idx >> 8) & 127;
    const int b   = idx >> 15;
    const int h = col >> 5, d = col & 31;

    const float* wrow = w_out + co * HID + h * DHEAD;
    const float* cr = g_ctx + ((b * NHEAD + h) * DHEAD + d) * DHEAD;
    float s = 0.f;
    #pragma unroll
    for (int e = 0; e < 32; ++e) s = fmaf(wrow[e], cr[e], s);
    const float m = s / g_ksum[b * HID + col];

    const long long o = ((long long)b * CIN + co) * HID + col;
    const __nv_bfloat16 hi = __float2bfloat16(m);
    g_M_hi[o] = hi;
    g_M_lo[o] = __float2bfloat16(m - __bfloat162float(hi));
}

// =====================================================================
extern "C" void kernel_launch(void* const* d_in, const int* in_sizes, int n_in,
                              void* d_out, int out_size)
{
    const float* x     = (const float*)d_in[0];   // [4,128,32768]
    const float* w_qkv = (const float*)d_in[1];   // [768,128]
    const float* w_out = (const float*)d_in[2];   // [128,256]
    const float* b_out = (const float*)d_in[3];   // [128]
    float* out = (float*)d_out;                   // [4,128,32768]

    float *qkv_p = nullptr, *ctx_p = nullptr, *ksum_p = nullptr;
    __nv_bfloat16 *xth, *xtl, *wqh, *wql, *qth, *qtl, *mh, *ml;
    cudaGetSymbolAddress((void**)&qkv_p, g_qkv);
    cudaGetSymbolAddress((void**)&ctx_p, g_ctx);
    cudaGetSymbolAddress((void**)&ksum_p, g_ksum);
    cudaGetSymbolAddress((void**)&xth, g_xt_hi);
    cudaGetSymbolAddress((void**)&xtl, g_xt_lo);
    cudaGetSymbolAddress((void**)&wqh, g_wq_hi);
    cudaGetSymbolAddress((void**)&wql, g_wq_lo);
    cudaGetSymbolAddress((void**)&qth, g_qt_hi);
    cudaGetSymbolAddress((void**)&qtl, g_qt_lo);
    cudaGetSymbolAddress((void**)&mh, g_M_hi);
    cudaGetSymbolAddress((void**)&ml, g_M_lo);

    // 0) convert inputs to bf16 hi/lo (x transposed)
    convx_kernel<<<dim3(NTOK / 32, CIN / 32, NB), dim3(32, 8)>>>(x);
    convw_kernel<<<(OQKV * CIN) / 256, 256>>>(w_qkv);

    // 1) qkv = W_qkv @ x  (HMMA, 3-term bf16 split), fp32 out -> g_qkv
    gemm_mma_kernel<false><<<dim3(NTOK / 128, OQKV / 128, NB), 256>>>(
        wqh, wql, xth, xtl, qkv_p, nullptr, CIN,
        0LL, (long long)NTOK * CIN, (long long)OQKV * NTOK);

    // 2) q softmax -> transposed bf16 hi/lo (smem-staged coalesced writes)
    qsoftmax_kernel<<<dim3(NTOK / 32, NB), 256>>>();

    // 3) zero accumulators
    cudaMemsetAsync(ctx_p, 0, sizeof(float) * NB * NHEAD * DHEAD * DHEAD);
    cudaMemsetAsync(ksum_p, 0, sizeof(float) * NB * HID);

    // 4) context + ksum (FFMA2, 64-n slabs)
    context_kernel<<<dim3(32, NHEAD, NB), 256>>>();

    // 5) fold projection matrix -> bf16 hi/lo
    mcombine_kernel<<<(NB * CIN * HID) / 256, 256>>>(w_out);

    // 6) out = M @ q_soft + b_out  (HMMA, K=256)
    gemm_mma_kernel<true><<<dim3(NTOK / 128, 1, NB), 256>>>(
        mh, ml, qth, qtl, out, b_out, HID,
        (long long)CIN * HID, (long long)NTOK * HID, (long long)CIN * NTOK);
}

// round 12
// speedup vs baseline: 1.0966x; 1.0292x over previous
#include <cuda_runtime.h>
#include <cuda_bf16.h>
#include <math.h>
#include <stdint.h>

#define NTOK  32768      // n = d*h*w
#define CIN   128        // channels
#define HID   256        // heads * dim_head
#define OQKV  768        // 3 * HID
#define NB    4          // batch
#define NHEAD 8
#define DHEAD 32
#define SCALE 0.1767766952966369f  // 32^-0.5

// ---------------- scratch (device globals: allocation-free rule) ----------------
__device__ __align__(256) float g_qkv[NB * HID * NTOK];            // q fp32 only, [b][hd][n]
__device__ __align__(256) __nv_bfloat16 g_kv16[NB * 2 * HID * NTOK]; // k|v bf16, [b][o-256][n]
__device__ __align__(256) float g_ksum[NB * HID];                  // per (b,h,d): sum exp(k)
__device__ __align__(256) float g_ctx[NB * NHEAD * DHEAD * DHEAD]; // raw sum exp(k)*v
__device__ __align__(256) __nv_bfloat16 g_xt_hi[NB * NTOK * CIN];  // x^T hi  [b][n][c]
__device__ __align__(256) __nv_bfloat16 g_xt_lo[NB * NTOK * CIN];  // x^T lo
__device__ __align__(256) __nv_bfloat16 g_wq_hi[OQKV * CIN];       // W_qkv hi [o][c]
__device__ __align__(256) __nv_bfloat16 g_wq_lo[OQKV * CIN];
__device__ __align__(256) __nv_bfloat16 g_qt_hi[NB * NTOK * HID];  // q_soft^T hi [b][n][hd]
__device__ __align__(256) __nv_bfloat16 g_qt_lo[NB * NTOK * HID];
__device__ __align__(256) __nv_bfloat16 g_M_hi[NB * CIN * HID];    // folded proj hi [b][co][hd]
__device__ __align__(256) __nv_bfloat16 g_M_lo[NB * CIN * HID];

// ====================== mma.sync helpers (baseline PTX, no 'a' features) ======================
__device__ __forceinline__ uint32_t smem_u32(const void* p) {
    uint32_t a;
    asm("{ .reg .u64 t; cvta.to.shared.u64 t, %1; cvt.u32.u64 %0, t; }" : "=r"(a) : "l"(p));
    return a;
}
__device__ __forceinline__ void ldsm4(uint32_t a, uint32_t* r) {
    asm volatile("ldmatrix.sync.aligned.m8n8.x4.shared.b16 {%0,%1,%2,%3}, [%4];"
                 : "=r"(r[0]), "=r"(r[1]), "=r"(r[2]), "=r"(r[3]) : "r"(a));
}
__device__ __forceinline__ void ldsm2(uint32_t a, uint32_t* r) {
    asm volatile("ldmatrix.sync.aligned.m8n8.x2.shared.b16 {%0,%1}, [%2];"
                 : "=r"(r[0]), "=r"(r[1]) : "r"(a));
}
__device__ __forceinline__ void mma_bf16(float* c, const uint32_t* a, const uint32_t* b) {
    asm volatile("mma.sync.aligned.m16n8k16.row.col.f32.bf16.bf16.f32 "
                 "{%0,%1,%2,%3}, {%4,%5,%6,%7}, {%8,%9}, {%0,%1,%2,%3};"
                 : "+f"(c[0]), "+f"(c[1]), "+f"(c[2]), "+f"(c[3])
                 : "r"(a[0]), "r"(a[1]), "r"(a[2]), "r"(a[3]), "r"(b[0]), "r"(b[1]));
}

// =====================================================================
// HMMA GEMM with bf16 hi/lo split (3 product terms, fp32 accumulate):
//   C[128 x 128] tile = A[128 x K] @ B[128 x K]^T
// 256 threads = 8 warps (2 m x 4 n), warp tile 64x32, BK=32 chunks with
// register-prefetch. KVSPLIT (GEMM1): grid is (mt, nt, b) so the 6 CTAs
// sharing a B tile run back-to-back (B read once from DRAM, then L2);
// m-tiles 0-1 write q fp32 to C, m-tiles 2-5 write k/v as bf16 to KV.
// =====================================================================
#define LDT 40   // padded row stride in bf16 elements

template<bool BIAS, bool KVSPLIT>
__global__ __launch_bounds__(256, 1)
void gemm_mma_kernel(const __nv_bfloat16* __restrict__ Ahi, const __nv_bfloat16* __restrict__ Alo,
                     const __nv_bfloat16* __restrict__ Bhi, const __nv_bfloat16* __restrict__ Blo,
                     float* __restrict__ C, const float* __restrict__ bias,
                     __nv_bfloat16* __restrict__ KV, int K,
                     long long sA, long long sB, long long sC)
{
    __shared__ __align__(16) __nv_bfloat16 sm[4][128 * LDT];  // Ah, Al, Bh, Bl

    const int tid = threadIdx.x, wid = tid >> 5, lane = tid & 31;
    const int mt = KVSPLIT ? blockIdx.x : blockIdx.y;
    const int nt = KVSPLIT ? blockIdx.y : blockIdx.x;
    const int b  = blockIdx.z;

    const __nv_bfloat16* Ah = Ahi + (long long)b * sA + (long long)mt * 128 * K;
    const __nv_bfloat16* Al = Alo + (long long)b * sA + (long long)mt * 128 * K;
    const __nv_bfloat16* Bh = Bhi + (long long)b * sB + (long long)nt * 128 * K;
    const __nv_bfloat16* Bl = Blo + (long long)b * sB + (long long)nt * 128 * K;
    float* Cb = C + (long long)b * sC + (long long)mt * 128 * NTOK + (long long)nt * 128;

    const int r0c = tid >> 2,         k80 = (tid & 3) << 3;
    const int r1c = (tid + 256) >> 2, k81 = ((tid + 256) & 3) << 3;

    uint4 p[4][2];
    {
        const long long o0 = (long long)r0c * K + k80;
        const long long o1 = (long long)r1c * K + k81;
        p[0][0] = *(const uint4*)(Ah + o0); p[0][1] = *(const uint4*)(Ah + o1);
        p[1][0] = *(const uint4*)(Al + o0); p[1][1] = *(const uint4*)(Al + o1);
        p[2][0] = *(const uint4*)(Bh + o0); p[2][1] = *(const uint4*)(Bh + o1);
        p[3][0] = *(const uint4*)(Bl + o0); p[3][1] = *(const uint4*)(Bl + o1);
    }

    float acc[4][4][4];
    #pragma unroll
    for (int mi = 0; mi < 4; ++mi)
        #pragma unroll
        for (int ni = 0; ni < 4; ++ni)
            #pragma unroll
            for (int e = 0; e < 4; ++e)
                acc[mi][ni][e] = 0.f;

    const int m0 = (wid & 1) * 64;
    const int n0 = (wid >> 1) * 32;

    uint32_t baseA_h = smem_u32(&sm[0][0]);
    uint32_t baseA_l = smem_u32(&sm[1][0]);
    uint32_t baseB_h = smem_u32(&sm[2][0]);
    uint32_t baseB_l = smem_u32(&sm[3][0]);

    const int d0 = r0c * LDT + k80;
    const int d1 = r1c * LDT + k81;

    const int nkc = K >> 5;
    for (int kc = 0; kc < nkc; ++kc) {
        #pragma unroll
        for (int t = 0; t < 4; ++t) {
            *(uint4*)&sm[t][d0] = p[t][0];
            *(uint4*)&sm[t][d1] = p[t][1];
        }
        __syncthreads();

        if (kc + 1 < nkc) {
            const long long o0 = (long long)r0c * K + (kc + 1) * 32 + k80;
            const long long o1 = (long long)r1c * K + (kc + 1) * 32 + k81;
            p[0][0] = *(const uint4*)(Ah + o0); p[0][1] = *(const uint4*)(Ah + o1);
            p[1][0] = *(const uint4*)(Al + o0); p[1][1] = *(const uint4*)(Al + o1);
            p[2][0] = *(const uint4*)(Bh + o0); p[2][1] = *(const uint4*)(Bh + o1);
            p[3][0] = *(const uint4*)(Bl + o0); p[3][1] = *(const uint4*)(Bl + o1);
        }

        #pragma unroll
        for (int s = 0; s < 2; ++s) {
            const uint32_t aoff = (uint32_t)((m0 + (lane & 15)) * (LDT * 2)
                                 + s * 32 + ((lane >> 4) << 4));
            const uint32_t boff = (uint32_t)((n0 + (lane & 7)) * (LDT * 2)
                                 + s * 32 + (((lane >> 3) & 1) << 4));
            uint32_t ah[4][4], al[4][4], bh[4][2], bl[4][2];
            #pragma unroll
            for (int mi = 0; mi < 4; ++mi) {
                ldsm4(baseA_h + aoff + mi * 16 * (LDT * 2), ah[mi]);
                ldsm4(baseA_l + aoff + mi * 16 * (LDT * 2), al[mi]);
            }
            #pragma unroll
            for (int ni = 0; ni < 4; ++ni) {
                ldsm2(baseB_h + boff + ni * 8 * (LDT * 2), bh[ni]);
                ldsm2(baseB_l + boff + ni * 8 * (LDT * 2), bl[ni]);
            }
            #pragma unroll
            for (int mi = 0; mi < 4; ++mi)
                #pragma unroll
                for (int ni = 0; ni < 4; ++ni) {
                    mma_bf16(acc[mi][ni], ah[mi], bh[ni]);
                    mma_bf16(acc[mi][ni], al[mi], bh[ni]);
                    mma_bf16(acc[mi][ni], ah[mi], bl[ni]);
                }
        }
        __syncthreads();
    }

    if (KVSPLIT && mt >= 2) {
        // k/v tiles -> bf16 [b][o-256][n]
        __nv_bfloat16* kvb = KV + ((long long)b * 2 * HID + (long long)(mt - 2) * 128) * NTOK
                           + (long long)nt * 128;
        #pragma unroll
        for (int mi = 0; mi < 4; ++mi) {
            const int r = m0 + mi * 16 + (lane >> 2);
            #pragma unroll
            for (int ni = 0; ni < 4; ++ni) {
                const int cc = n0 + ni * 8 + ((lane & 3) << 1);
                __nv_bfloat162 w0 = __floats2bfloat162_rn(acc[mi][ni][0], acc[mi][ni][1]);
                __nv_bfloat162 w1 = __floats2bfloat162_rn(acc[mi][ni][2], acc[mi][ni][3]);
                *(__nv_bfloat162*)(kvb + (long long)r * NTOK + cc)       = w0;
                *(__nv_bfloat162*)(kvb + (long long)(r + 8) * NTOK + cc) = w1;
            }
        }
        return;
    }

    // fp32 epilogue (q tiles and GEMM2)
    #pragma unroll
    for (int mi = 0; mi < 4; ++mi) {
        const int r = m0 + mi * 16 + (lane >> 2);
        const float bv0 = BIAS ? bias[mt * 128 + r] : 0.f;
        const float bv1 = BIAS ? bias[mt * 128 + r + 8] : 0.f;
        #pragma unroll
        for (int ni = 0; ni < 4; ++ni) {
            const int cc = n0 + ni * 8 + ((lane & 3) << 1);
            float2 v0 = make_float2(acc[mi][ni][0] + bv0, acc[mi][ni][1] + bv0);
            float2 v1 = make_float2(acc[mi][ni][2] + bv1, acc[mi][ni][3] + bv1);
            *(float2*)(Cb + (long long)r * NTOK + cc)       = v0;
            *(float2*)(Cb + (long long)(r + 8) * NTOK + cc) = v1;
        }
    }
}

// =====================================================================
// x [b][c][n] fp32 -> x^T hi/lo bf16 [b][n][c]   (32x32 smem transpose)
// =====================================================================
__global__ void convx_kernel(const float* __restrict__ x)
{
    __shared__ float t[32][33];
    const int n0 = blockIdx.x * 32, c0 = blockIdx.y * 32, b = blockIdx.z;
    const int tx = threadIdx.x, ty = threadIdx.y;
    const float* xb = x + ((long long)b * CIN + c0) * NTOK + n0;
    #pragma unroll
    for (int i = 0; i < 4; ++i)
        t[ty + i * 8][tx] = xb[(long long)(ty + i * 8) * NTOK + tx];
    __syncthreads();
    #pragma unroll
    for (int i = 0; i < 4; ++i) {
        const int n = ty + i * 8;
        const float v = t[tx][n];
        const __nv_bfloat16 hi = __float2bfloat16(v);
        const __nv_bfloat16 lo = __float2bfloat16(v - __bfloat162float(hi));
        const long long o = ((long long)b * NTOK + n0 + n) * CIN + c0 + tx;
        g_xt_hi[o] = hi;
        g_xt_lo[o] = lo;
    }
}

// W_qkv [768][128] fp32 -> hi/lo bf16 same layout
__global__ void convw_kernel(const float* __restrict__ w)
{
    const int i = blockIdx.x * 256 + threadIdx.x;
    const float v = w[i];
    const __nv_bfloat16 hi = __float2bfloat16(v);
    g_wq_hi[i] = hi;
    g_wq_lo[i] = __float2bfloat16(v - __bfloat162float(hi));
}

// =====================================================================
// q softmax over the 32 feature dims of each head, * SCALE; writes
// transposed bf16 hi/lo [b][n][h*32+d]  (R6-proven version).
// =====================================================================
__global__ void qsoftmax_kernel()
{
    const int idx = blockIdx.x * blockDim.x + threadIdx.x;  // 4*8*32768
    const int n  = idx & (NTOK - 1);
    const int hb = idx >> 15;
    const int h  = hb & (NHEAD - 1);
    const int b  = hb >> 3;

    const float* qp = g_qkv + ((long long)b * HID + (long long)h * DHEAD) * NTOK + n;

    float v[32];
    float m = -1e30f;
    #pragma unroll
    for (int d = 0; d < 32; ++d) {
        v[d] = qp[(long long)d * NTOK];
        m = fmaxf(m, v[d]);
    }
    float s = 0.f;
    #pragma unroll
    for (int d = 0; d < 32; ++d) {
        v[d] = __expf(v[d] - m);
        s += v[d];
    }
    const float inv = SCALE / s;

    __align__(16) __nv_bfloat16 hb16[32], lb16[32];
    #pragma unroll
    for (int d = 0; d < 32; ++d) {
        const float q = v[d] * inv;
        const __nv_bfloat16 hi = __float2bfloat16(q);
        hb16[d] = hi;
        lb16[d] = __float2bfloat16(q - __bfloat162float(hi));
    }
    const long long o = ((long long)b * NTOK + n) * HID + h * DHEAD;
    #pragma unroll
    for (int j = 0; j < 4; ++j) {
        *(uint4*)(&g_qt_hi[o + j * 8]) = ((const uint4*)hb16)[j];
        *(uint4*)(&g_qt_lo[o + j * 8]) = ((const uint4*)lb16)[j];
    }
}

// =====================================================================
// context: ctx[b,h,d,e] += sum_n exp(k[d,n]) * v[e,n];  ksum += sum exp(k)
// k,v read as bf16 (half the DRAM traffic). FFMA2 inner loop, 64-n slabs.
// Grid (32 n-chunks, NHEAD, NB), 256 threads.
// =====================================================================
__device__ __forceinline__ void bf8_to_f8(uint4 u, float* f) {
    const __nv_bfloat162* h2 = (const __nv_bfloat162*)&u;
    #pragma unroll
    for (int j = 0; j < 4; ++j) {
        float2 t = __bfloat1622float2(h2[j]);
        f[2 * j] = t.x; f[2 * j + 1] = t.y;
    }
}

__global__ __launch_bounds__(256, 2)
void context_kernel()
{
    const int b = blockIdx.z, h = blockIdx.y, cx = blockIdx.x;
    const int t = threadIdx.x;
    const __nv_bfloat16* kbase = g_kv16 + ((long long)b * 2 * HID + h * DHEAD) * NTOK;
    const __nv_bfloat16* vbase = kbase + (long long)HID * NTOK;

    __shared__ float ks[32][65];   // [d][n]
    __shared__ float vt[64][34];   // [n][e]
    __shared__ float red[32][33];

    for (int i = t; i < 1024; i += 256) red[i >> 5][i & 31] = 0.f;

    const int ld = t >> 3;            // loader d row 0..31
    const int ln = (t & 7) << 3;      // loader 8 consecutive n
    const int slot = t >> 4;
    const int l    = t & 15;
    const int ti   = l >> 2;
    const int tj   = l & 3;

    unsigned long long accp[8][4];
    #pragma unroll
    for (int i = 0; i < 8; ++i)
        #pragma unroll
        for (int j = 0; j < 4; ++j)
            accp[i][j] = 0ULL;
    float ksum_part = 0.f;

    const int nchunk = NTOK / 32;
    const int nbase0 = cx * nchunk;
    const int NS = nchunk / 64;       // 16 slabs of 64 n

    const __nv_bfloat16* krow = kbase + (long long)ld * NTOK + nbase0 + ln;
    const __nv_bfloat16* vrow = vbase + (long long)ld * NTOK + nbase0 + ln;
    uint4 kr = *(const uint4*)krow;
    uint4 vr = *(const uint4*)vrow;

    for (int slab = 0; slab < NS; ++slab) {
        float kf[8], vf[8];
        bf8_to_f8(kr, kf);
        bf8_to_f8(vr, vf);
        float e[8];
        #pragma unroll
        for (int j = 0; j < 8; ++j) e[j] = __expf(kf[j]);
        ksum_part += ((e[0] + e[1]) + (e[2] + e[3])) + ((e[4] + e[5]) + (e[6] + e[7]));
        #pragma unroll
        for (int j = 0; j < 8; ++j) {
            ks[ld][ln + j] = e[j];
            vt[ln + j][ld] = vf[j];
        }
        __syncthreads();

        if (slab + 1 < NS) {
            kr = *(const uint4*)(krow + (slab + 1) * 64);
            vr = *(const uint4*)(vrow + (slab + 1) * 64);
        }

        #pragma unroll
        for (int q = 0; q < 4; ++q) {
            const int n = slot + (q << 4);
            unsigned long long a2[8];
            #pragma unroll
            for (int i = 0; i < 8; ++i) {
                const float ka = ks[ti * 8 + i][n];
                asm("mov.b64 %0, {%1, %1};" : "=l"(a2[i]) : "f"(ka));
            }
            unsigned long long vb[4];
            #pragma unroll
            for (int j = 0; j < 4; ++j)
                vb[j] = *(const unsigned long long*)&vt[n][tj * 8 + 2 * j];
            #pragma unroll
            for (int i = 0; i < 8; ++i)
                #pragma unroll
                for (int j = 0; j < 4; ++j)
                    asm("fma.rn.f32x2 %0, %1, %2, %0;"
                        : "+l"(accp[i][j]) : "l"(a2[i]), "l"(vb[j]));
        }
        __syncthreads();
    }

    #pragma unroll
    for (int o = 4; o > 0; o >>= 1)
        ksum_part += __shfl_down_sync(0xffffffffu, ksum_part, o, 8);
    if ((t & 7) == 0)
        atomicAdd(&g_ksum[(b * NHEAD + h) * DHEAD + ld], ksum_part);

    #pragma unroll
    for (int i = 0; i < 8; ++i)
        #pragma unroll
        for (int j = 0; j < 4; ++j) {
            float f0, f1;
            asm("mov.b64 {%0, %1}, %2;" : "=f"(f0), "=f"(f1) : "l"(accp[i][j]));
            atomicAdd(&red[ti * 8 + i][tj * 8 + 2 * j],     f0);
            atomicAdd(&red[ti * 8 + i][tj * 8 + 2 * j + 1], f1);
        }
    __syncthreads();

    float* ctx = g_ctx + (b * NHEAD + h) * (DHEAD * DHEAD);
    for (int i = t; i < 1024; i += 256)
        atomicAdd(&ctx[i], red[i >> 5][i & 31]);
}

// =====================================================================
// M[b][co][h*32+d] = (sum_e W_out[co][h*32+e] * ctx[b,h,d,e]) / ksum[b,h,d]
// emitted as bf16 hi/lo for GEMM2's A operand.
// =====================================================================
__global__ void mcombine_kernel(const float* __restrict__ w_out)
{
    const int idx = blockIdx.x * 256 + threadIdx.x;   // 4*128*256
    const int col = idx & 255;
    const int co  = (idx >> 8) & 127;
    const int b   = idx >> 15;
    const int h = col >> 5, d = col & 31;

    const float* wrow = w_out + co * HID + h * DHEAD;
    const float* cr = g_ctx + ((b * NHEAD + h) * DHEAD + d) * DHEAD;
    float s = 0.f;
    #pragma unroll
    for (int e = 0; e < 32; ++e) s = fmaf(wrow[e], cr[e], s);
    const float m = s / g_ksum[b * HID + col];

    const long long o = ((long long)b * CIN + co) * HID + col;
    const __nv_bfloat16 hi = __float2bfloat16(m);
    g_M_hi[o] = hi;
    g_M_lo[o] = __float2bfloat16(m - __bfloat162float(hi));
}

// =====================================================================
extern "C" void kernel_launch(void* const* d_in, const int* in_sizes, int n_in,
                              void* d_out, int out_size)
{
    const float* x     = (const float*)d_in[0];   // [4,128,32768]
    const float* w_qkv = (const float*)d_in[1];   // [768,128]
    const float* w_out = (const float*)d_in[2];   // [128,256]
    const float* b_out = (const float*)d_in[3];   // [128]
    float* out = (float*)d_out;                   // [4,128,32768]

    float *qkv_p = nullptr, *ctx_p = nullptr, *ksum_p = nullptr;
    __nv_bfloat16 *kv16, *xth, *xtl, *wqh, *wql, *qth, *qtl, *mh, *ml;
    cudaGetSymbolAddress((void**)&qkv_p, g_qkv);
    cudaGetSymbolAddress((void**)&kv16, g_kv16);
    cudaGetSymbolAddress((void**)&ctx_p, g_ctx);
    cudaGetSymbolAddress((void**)&ksum_p, g_ksum);
    cudaGetSymbolAddress((void**)&xth, g_xt_hi);
    cudaGetSymbolAddress((void**)&xtl, g_xt_lo);
    cudaGetSymbolAddress((void**)&wqh, g_wq_hi);
    cudaGetSymbolAddress((void**)&wql, g_wq_lo);
    cudaGetSymbolAddress((void**)&qth, g_qt_hi);
    cudaGetSymbolAddress((void**)&qtl, g_qt_lo);
    cudaGetSymbolAddress((void**)&mh, g_M_hi);
    cudaGetSymbolAddress((void**)&ml, g_M_lo);

    // 0) convert inputs to bf16 hi/lo (x transposed)
    convx_kernel<<<dim3(NTOK / 32, CIN / 32, NB), dim3(32, 8)>>>(x);
    convw_kernel<<<(OQKV * CIN) / 256, 256>>>(w_qkv);

    // 1) qkv = W_qkv @ x  (HMMA, 3-term bf16 split).
    //    grid (mt, nt, b): B-tile reuse lands in L2.
    //    q (mt 0-1) -> fp32 g_qkv; k,v (mt 2-5) -> bf16 g_kv16.
    gemm_mma_kernel<false, true><<<dim3(OQKV / 128, NTOK / 128, NB), 256>>>(
        wqh, wql, xth, xtl, qkv_p, nullptr, kv16, CIN,
        0LL, (long long)NTOK * CIN, (long long)HID * NTOK);

    // 2) q softmax -> transposed bf16 hi/lo
    qsoftmax_kernel<<<(NB * NHEAD * NTOK) / 256, 256>>>();

    // 3) zero accumulators
    cudaMemsetAsync(ctx_p, 0, sizeof(float) * NB * NHEAD * DHEAD * DHEAD);
    cudaMemsetAsync(ksum_p, 0, sizeof(float) * NB * HID);

    // 4) context + ksum (bf16 k/v, FFMA2, 64-n slabs)
    context_kernel<<<dim3(32, NHEAD, NB), 256>>>();

    // 5) fold projection matrix -> bf16 hi/lo
    mcombine_kernel<<<(NB * CIN * HID) / 256, 256>>>(w_out);

    // 6) out = M @ q_soft + b_out  (HMMA, K=256)
    gemm_mma_kernel<true, false><<<dim3(NTOK / 128, 1, NB), 256>>>(
        mh, ml, qth, qtl, out, b_out, nullptr, HID,
        (long long)CIN * HID, (long long)NTOK * HID, (long long)CIN * NTOK);
}

// round 17
// speedup vs baseline: 1.4782x; 1.3479x over previous
#include <cuda_runtime.h>
#include <cuda_fp16.h>
#include <math.h>
#include <stdint.h>

#define NTOK  32768      // n = d*h*w
#define CIN   128        // channels
#define HID   256        // heads * dim_head
#define OQKV  768        // 3 * HID
#define NB    4          // batch
#define NHEAD 8
#define DHEAD 32
#define SCALE 0.1767766952966369f  // 32^-0.5

// ---------------- scratch (device globals: allocation-free rule) ----------------
__device__ __align__(256) float  g_qkv[NB * HID * NTOK];            // q fp32, [b][hd][n]
__device__ __align__(256) __half g_kv16[NB * 2 * HID * NTOK];       // k|v fp16, [b][o-256][n]
__device__ __align__(256) float  g_ksum[NB * HID];                  // per (b,h,d): sum exp(k)
__device__ __align__(256) float  g_ctx[NB * NHEAD * DHEAD * DHEAD]; // raw sum exp(k)*v
__device__ __align__(256) __half g_xt[NB * NTOK * CIN];             // x^T fp16 [b][n][c]
__device__ __align__(256) __half g_wq[OQKV * CIN];                  // W_qkv fp16 [o][c]
__device__ __align__(256) __half g_qt[NB * NTOK * HID];             // q_soft^T fp16 [b][n][hd]
__device__ __align__(256) __half g_M_hi[NB * CIN * HID];            // folded proj hi [b][co][hd]
__device__ __align__(256) __half g_M_lo[NB * CIN * HID];            // folded proj lo

// ====================== mma.sync helpers (baseline PTX, no 'a' features) ======================
__device__ __forceinline__ uint32_t smem_u32(const void* p) {
    uint32_t a;
    asm("{ .reg .u64 t; cvta.to.shared.u64 t, %1; cvt.u32.u64 %0, t; }" : "=r"(a) : "l"(p));
    return a;
}
__device__ __forceinline__ void ldsm4(uint32_t a, uint32_t* r) {
    asm volatile("ldmatrix.sync.aligned.m8n8.x4.shared.b16 {%0,%1,%2,%3}, [%4];"
                 : "=r"(r[0]), "=r"(r[1]), "=r"(r[2]), "=r"(r[3]) : "r"(a));
}
__device__ __forceinline__ void ldsm2(uint32_t a, uint32_t* r) {
    asm volatile("ldmatrix.sync.aligned.m8n8.x2.shared.b16 {%0,%1}, [%2];"
                 : "=r"(r[0]), "=r"(r[1]) : "r"(a));
}
__device__ __forceinline__ void mma_f16(float* c, const uint32_t* a, const uint32_t* b) {
    asm volatile("mma.sync.aligned.m16n8k16.row.col.f32.f16.f16.f32 "
                 "{%0,%1,%2,%3}, {%4,%5,%6,%7}, {%8,%9}, {%0,%1,%2,%3};"
                 : "+f"(c[0]), "+f"(c[1]), "+f"(c[2]), "+f"(c[3])
                 : "r"(a[0]), "r"(a[1]), "r"(a[2]), "r"(a[3]), "r"(b[0]), "r"(b[1]));
}

// =====================================================================
// fp16 HMMA GEMM: C[128 x 128] tile = A[128 x K] @ B[128 x K]^T
// ASPLIT = number of A streams (1 = plain fp16, 2 = hi/lo split, fp32 acc).
// 256 threads = 8 warps (2 m x 4 n), warp tile 64x32, BK=32 chunks with
// register-prefetch. KVSPLIT (GEMM1): grid (mt, nt, b) so the 6 CTAs
// sharing a B tile run back-to-back (B hits L2); m-tiles 0-1 write q
// fp32 to C, m-tiles 2-5 write k/v fp16 to KV.
// =====================================================================
#define LDT 40   // padded row stride in fp16 elements

template<int ASPLIT, bool BIAS, bool KVSPLIT>
__global__ __launch_bounds__(256, 1)
void gemm_mma_kernel(const __half* __restrict__ A0, const __half* __restrict__ A1,
                     const __half* __restrict__ B0,
                     float* __restrict__ C, const float* __restrict__ bias,
                     __half* __restrict__ KV, int K,
                     long long sA, long long sB, long long sC)
{
    constexpr int NT = ASPLIT + 1;
    __shared__ __align__(16) __half sm[NT][128 * LDT];

    const int tid = threadIdx.x, wid = tid >> 5, lane = tid & 31;
    const int mt = KVSPLIT ? blockIdx.x : blockIdx.y;
    const int nt = KVSPLIT ? blockIdx.y : blockIdx.x;
    const int b  = blockIdx.z;

    const __half* src[NT];
    {
        const long long aoff = (long long)b * sA + (long long)mt * 128 * K;
        const long long boff = (long long)b * sB + (long long)nt * 128 * K;
        src[0] = A0 + aoff;
        if (ASPLIT == 2) src[1] = A1 + aoff;
        src[NT - 1] = B0 + boff;
    }
    float* Cb = C + (long long)b * sC + (long long)mt * 128 * NTOK + (long long)nt * 128;

    const int r0c = tid >> 2,         k80 = (tid & 3) << 3;
    const int r1c = (tid + 256) >> 2, k81 = ((tid + 256) & 3) << 3;

    uint4 p[NT][2];
    {
        const long long o0 = (long long)r0c * K + k80;
        const long long o1 = (long long)r1c * K + k81;
        #pragma unroll
        for (int t = 0; t < NT; ++t) {
            p[t][0] = *(const uint4*)(src[t] + o0);
            p[t][1] = *(const uint4*)(src[t] + o1);
        }
    }

    float acc[4][4][4];
    #pragma unroll
    for (int mi = 0; mi < 4; ++mi)
        #pragma unroll
        for (int ni = 0; ni < 4; ++ni)
            #pragma unroll
            for (int e = 0; e < 4; ++e)
                acc[mi][ni][e] = 0.f;

    const int m0 = (wid & 1) * 64;
    const int n0 = (wid >> 1) * 32;

    uint32_t sb[NT];
    #pragma unroll
    for (int t = 0; t < NT; ++t) sb[t] = smem_u32(&sm[t][0]);

    const int d0 = r0c * LDT + k80;
    const int d1 = r1c * LDT + k81;

    const int nkc = K >> 5;
    for (int kc = 0; kc < nkc; ++kc) {
        #pragma unroll
        for (int t = 0; t < NT; ++t) {
            *(uint4*)&sm[t][d0] = p[t][0];
            *(uint4*)&sm[t][d1] = p[t][1];
        }
        __syncthreads();

        if (kc + 1 < nkc) {
            const long long o0 = (long long)r0c * K + (kc + 1) * 32 + k80;
            const long long o1 = (long long)r1c * K + (kc + 1) * 32 + k81;
            #pragma unroll
            for (int t = 0; t < NT; ++t) {
                p[t][0] = *(const uint4*)(src[t] + o0);
                p[t][1] = *(const uint4*)(src[t] + o1);
            }
        }

        #pragma unroll
        for (int s = 0; s < 2; ++s) {
            const uint32_t aoff = (uint32_t)((m0 + (lane & 15)) * (LDT * 2)
                                 + s * 32 + ((lane >> 4) << 4));
            const uint32_t boff = (uint32_t)((n0 + (lane & 7)) * (LDT * 2)
                                 + s * 32 + (((lane >> 3) & 1) << 4));
            uint32_t afr[ASPLIT][4][4], bfr[4][2];
            #pragma unroll
            for (int sp = 0; sp < ASPLIT; ++sp)
                #pragma unroll
                for (int mi = 0; mi < 4; ++mi)
                    ldsm4(sb[sp] + aoff + mi * 16 * (LDT * 2), afr[sp][mi]);
            #pragma unroll
            for (int ni = 0; ni < 4; ++ni)
                ldsm2(sb[NT - 1] + boff + ni * 8 * (LDT * 2), bfr[ni]);
            #pragma unroll
            for (int mi = 0; mi < 4; ++mi)
                #pragma unroll
                for (int ni = 0; ni < 4; ++ni)
                    #pragma unroll
                    for (int sp = 0; sp < ASPLIT; ++sp)
                        mma_f16(acc[mi][ni], afr[sp][mi], bfr[ni]);
        }
        __syncthreads();
    }

    if (KVSPLIT && mt >= 2) {
        // k/v tiles -> fp16 [b][o-256][n]
        __half* kvb = KV + ((long long)b * 2 * HID + (long long)(mt - 2) * 128) * NTOK
                    + (long long)nt * 128;
        #pragma unroll
        for (int mi = 0; mi < 4; ++mi) {
            const int r = m0 + mi * 16 + (lane >> 2);
            #pragma unroll
            for (int ni = 0; ni < 4; ++ni) {
                const int cc = n0 + ni * 8 + ((lane & 3) << 1);
                __half2 w0 = __floats2half2_rn(acc[mi][ni][0], acc[mi][ni][1]);
                __half2 w1 = __floats2half2_rn(acc[mi][ni][2], acc[mi][ni][3]);
                *(__half2*)(kvb + (long long)r * NTOK + cc)       = w0;
                *(__half2*)(kvb + (long long)(r + 8) * NTOK + cc) = w1;
            }
        }
        return;
    }

    // fp32 epilogue (q tiles and GEMM2)
    #pragma unroll
    for (int mi = 0; mi < 4; ++mi) {
        const int r = m0 + mi * 16 + (lane >> 2);
        const float bv0 = BIAS ? bias[mt * 128 + r] : 0.f;
        const float bv1 = BIAS ? bias[mt * 128 + r + 8] : 0.f;
        #pragma unroll
        for (int ni = 0; ni < 4; ++ni) {
            const int cc = n0 + ni * 8 + ((lane & 3) << 1);
            float2 v0 = make_float2(acc[mi][ni][0] + bv0, acc[mi][ni][1] + bv0);
            float2 v1 = make_float2(acc[mi][ni][2] + bv1, acc[mi][ni][3] + bv1);
            *(float2*)(Cb + (long long)r * NTOK + cc)       = v0;
            *(float2*)(Cb + (long long)(r + 8) * NTOK + cc) = v1;
        }
    }
}

// =====================================================================
// x [b][c][n] fp32 -> x^T fp16 [b][n][c]   (32x32 smem transpose)
// =====================================================================
__global__ void convx_kernel(const float* __restrict__ x)
{
    __shared__ float t[32][33];
    const int n0 = blockIdx.x * 32, c0 = blockIdx.y * 32, b = blockIdx.z;
    const int tx = threadIdx.x, ty = threadIdx.y;
    const float* xb = x + ((long long)b * CIN + c0) * NTOK + n0;
    #pragma unroll
    for (int i = 0; i < 4; ++i)
        t[ty + i * 8][tx] = xb[(long long)(ty + i * 8) * NTOK + tx];
    __syncthreads();
    #pragma unroll
    for (int i = 0; i < 4; ++i) {
        const int n = ty + i * 8;
        g_xt[((long long)b * NTOK + n0 + n) * CIN + c0 + tx] = __float2half(t[tx][n]);
    }
}

// W_qkv [768][128] fp32 -> fp16 same layout
__global__ void convw_kernel(const float* __restrict__ w)
{
    const int i = blockIdx.x * 256 + threadIdx.x;
    g_wq[i] = __float2half(w[i]);
}

// =====================================================================
// q softmax over the 32 feature dims of each head, * SCALE; writes
// transposed fp16 [b][n][h*32+d].
// =====================================================================
__global__ void qsoftmax_kernel()
{
    const int idx = blockIdx.x * blockDim.x + threadIdx.x;  // 4*8*32768
    const int n  = idx & (NTOK - 1);
    const int hb = idx >> 15;
    const int h  = hb & (NHEAD - 1);
    const int b  = hb >> 3;

    const float* qp = g_qkv + ((long long)b * HID + (long long)h * DHEAD) * NTOK + n;

    float v[32];
    float m = -1e30f;
    #pragma unroll
    for (int d = 0; d < 32; ++d) {
        v[d] = qp[(long long)d * NTOK];
        m = fmaxf(m, v[d]);
    }
    float s = 0.f;
    #pragma unroll
    for (int d = 0; d < 32; ++d) {
        v[d] = __expf(v[d] - m);
        s += v[d];
    }
    const float inv = SCALE / s;

    __align__(16) __half o16[32];
    #pragma unroll
    for (int d = 0; d < 32; ++d)
        o16[d] = __float2half(v[d] * inv);
    const long long o = ((long long)b * NTOK + n) * HID + h * DHEAD;
    #pragma unroll
    for (int j = 0; j < 4; ++j)
        *(uint4*)(&g_qt[o + j * 8]) = ((const uint4*)o16)[j];
}

// =====================================================================
// context: ctx[b,h,d,e] += sum_n exp(k[d,n]) * v[e,n];  ksum += sum exp(k)
// k,v read as fp16. FFMA2 inner loop, 64-n slabs.
// Grid (32 n-chunks, NHEAD, NB), 256 threads.
// =====================================================================
__device__ __forceinline__ void h8_to_f8(uint4 u, float* f) {
    const __half2* h2 = (const __half2*)&u;
    #pragma unroll
    for (int j = 0; j < 4; ++j) {
        float2 t = __half22float2(h2[j]);
        f[2 * j] = t.x; f[2 * j + 1] = t.y;
    }
}

__global__ __launch_bounds__(256, 2)
void context_kernel()
{
    const int b = blockIdx.z, h = blockIdx.y, cx = blockIdx.x;
    const int t = threadIdx.x;
    const __half* kbase = g_kv16 + ((long long)b * 2 * HID + h * DHEAD) * NTOK;
    const __half* vbase = kbase + (long long)HID * NTOK;

    __shared__ float ks[32][65];   // [d][n]
    __shared__ float vt[64][34];   // [n][e]
    __shared__ float red[32][33];

    for (int i = t; i < 1024; i += 256) red[i >> 5][i & 31] = 0.f;

    const int ld = t >> 3;            // loader d row 0..31
    const int ln = (t & 7) << 3;      // loader 8 consecutive n
    const int slot = t >> 4;
    const int l    = t & 15;
    const int ti   = l >> 2;
    const int tj   = l & 3;

    unsigned long long accp[8][4];
    #pragma unroll
    for (int i = 0; i < 8; ++i)
        #pragma unroll
        for (int j = 0; j < 4; ++j)
            accp[i][j] = 0ULL;
    float ksum_part = 0.f;

    const int nchunk = NTOK / 32;
    const int nbase0 = cx * nchunk;
    const int NS = nchunk / 64;       // 16 slabs of 64 n

    const __half* krow = kbase + (long long)ld * NTOK + nbase0 + ln;
    const __half* vrow = vbase + (long long)ld * NTOK + nbase0 + ln;
    uint4 kr = *(const uint4*)krow;
    uint4 vr = *(const uint4*)vrow;

    for (int slab = 0; slab < NS; ++slab) {
        float kf[8], vf[8];
        h8_to_f8(kr, kf);
        h8_to_f8(vr, vf);
        float e[8];
        #pragma unroll
        for (int j = 0; j < 8; ++j) e[j] = __expf(kf[j]);
        ksum_part += ((e[0] + e[1]) + (e[2] + e[3])) + ((e[4] + e[5]) + (e[6] + e[7]));
        #pragma unroll
        for (int j = 0; j < 8; ++j) {
            ks[ld][ln + j] = e[j];
            vt[ln + j][ld] = vf[j];
        }
        __syncthreads();

        if (slab + 1 < NS) {
            kr = *(const uint4*)(krow + (slab + 1) * 64);
            vr = *(const uint4*)(vrow + (slab + 1) * 64);
        }

        #pragma unroll
        for (int q = 0; q < 4; ++q) {
            const int n = slot + (q << 4);
            unsigned long long a2[8];
            #pragma unroll
            for (int i = 0; i < 8; ++i) {
                const float ka = ks[ti * 8 + i][n];
                asm("mov.b64 %0, {%1, %1};" : "=l"(a2[i]) : "f"(ka));
            }
            unsigned long long vb[4];
            #pragma unroll
            for (int j = 0; j < 4; ++j)
                vb[j] = *(const unsigned long long*)&vt[n][tj * 8 + 2 * j];
            #pragma unroll
            for (int i = 0; i < 8; ++i)
                #pragma unroll
                for (int j = 0; j < 4; ++j)
                    asm("fma.rn.f32x2 %0, %1, %2, %0;"
                        : "+l"(accp[i][j]) : "l"(a2[i]), "l"(vb[j]));
        }
        __syncthreads();
    }

    #pragma unroll
    for (int o = 4; o > 0; o >>= 1)
        ksum_part += __shfl_down_sync(0xffffffffu, ksum_part, o, 8);
    if ((t & 7) == 0)
        atomicAdd(&g_ksum[(b * NHEAD + h) * DHEAD + ld], ksum_part);

    #pragma unroll
    for (int i = 0; i < 8; ++i)
        #pragma unroll
        for (int j = 0; j < 4; ++j) {
            float f0, f1;
            asm("mov.b64 {%0, %1}, %2;" : "=f"(f0), "=f"(f1) : "l"(accp[i][j]));
            atomicAdd(&red[ti * 8 + i][tj * 8 + 2 * j],     f0);
            atomicAdd(&red[ti * 8 + i][tj * 8 + 2 * j + 1], f1);
        }
    __syncthreads();

    float* ctx = g_ctx + (b * NHEAD + h) * (DHEAD * DHEAD);
    for (int i = t; i < 1024; i += 256)
        atomicAdd(&ctx[i], red[i >> 5][i & 31]);
}

// =====================================================================
// M[b][co][h*32+d] = (sum_e W_out[co][h*32+e] * ctx[b,h,d,e]) / ksum[b,h,d]
// emitted as fp16 hi/lo for GEMM2's A operand.
// =====================================================================
__global__ void mcombine_kernel(const float* __restrict__ w_out)
{
    const int idx = blockIdx.x * 256 + threadIdx.x;   // 4*128*256
    const int col = idx & 255;
    const int co  = (idx >> 8) & 127;
    const int b   = idx >> 15;
    const int h = col >> 5, d = col & 31;

    const float* wrow = w_out + co * HID + h * DHEAD;
    const float* cr = g_ctx + ((b * NHEAD + h) * DHEAD + d) * DHEAD;
    float s = 0.f;
    #pragma unroll
    for (int e = 0; e < 32; ++e) s = fmaf(wrow[e], cr[e], s);
    const float m = s / g_ksum[b * HID + col];

    const long long o = ((long long)b * CIN + co) * HID + col;
    const __half hi = __float2half(m);
    g_M_hi[o] = hi;
    g_M_lo[o] = __float2half(m - __half2float(hi));
}

// =====================================================================
extern "C" void kernel_launch(void* const* d_in, const int* in_sizes, int n_in,
                              void* d_out, int out_size)
{
    const float* x     = (const float*)d_in[0];   // [4,128,32768]
    const float* w_qkv = (const float*)d_in[1];   // [768,128]
    const float* w_out = (const float*)d_in[2];   // [128,256]
    const float* b_out = (const float*)d_in[3];   // [128]
    float* out = (float*)d_out;                   // [4,128,32768]

    float *qkv_p = nullptr, *ctx_p = nullptr, *ksum_p = nullptr;
    __half *kv16, *xt, *wq, *qt, *mh, *ml;
    cudaGetSymbolAddress((void**)&qkv_p, g_qkv);
    cudaGetSymbolAddress((void**)&kv16, g_kv16);
    cudaGetSymbolAddress((void**)&ctx_p, g_ctx);
    cudaGetSymbolAddress((void**)&ksum_p, g_ksum);
    cudaGetSymbolAddress((void**)&xt, g_xt);
    cudaGetSymbolAddress((void**)&wq, g_wq);
    cudaGetSymbolAddress((void**)&qt, g_qt);
    cudaGetSymbolAddress((void**)&mh, g_M_hi);
    cudaGetSymbolAddress((void**)&ml, g_M_lo);

    // 0) convert inputs to fp16 (x transposed)
    convx_kernel<<<dim3(NTOK / 32, CIN / 32, NB), dim3(32, 8)>>>(x);
    convw_kernel<<<(OQKV * CIN) / 256, 256>>>(w_qkv);

    // 1) qkv = W_qkv @ x  (single-term fp16 HMMA, fp32 accumulate).
    //    grid (mt, nt, b): B-tile reuse lands in L2.
    //    q (mt 0-1) -> fp32 g_qkv; k,v (mt 2-5) -> fp16 g_kv16.
    gemm_mma_kernel<1, false, true><<<dim3(OQKV / 128, NTOK / 128, NB), 256>>>(
        wq, nullptr, xt, qkv_p, nullptr, kv16, CIN,
        0LL, (long long)NTOK * CIN, (long long)HID * NTOK);

    // 2) q softmax -> transposed fp16
    qsoftmax_kernel<<<(NB * NHEAD * NTOK) / 256, 256>>>();

    // 3) zero accumulators
    cudaMemsetAsync(ctx_p, 0, sizeof(float) * NB * NHEAD * DHEAD * DHEAD);
    cudaMemsetAsync(ksum_p, 0, sizeof(float) * NB * HID);

    // 4) context + ksum (fp16 k/v, FFMA2, 64-n slabs)
    context_kernel<<<dim3(32, NHEAD, NB), 256>>>();

    // 5) fold projection matrix -> fp16 hi/lo
    mcombine_kernel<<<(NB * CIN * HID) / 256, 256>>>(w_out);

    // 6) out = M @ q_soft + b_out  (2-term fp16 HMMA: M hi/lo x q single, K=256)
    gemm_mma_kernel<2, true, false><<<dim3(NTOK / 128, 1, NB), 256>>>(
        mh, ml, qt, out, b_out, nullptr, HID,
        (long long)CIN * HID, (long long)NTOK * HID, (long long)CIN * NTOK);
}